// round 3
// baseline (speedup 1.0000x reference)
#include <cuda_runtime.h>
#include <cuda_bf16.h>
#include <stdint.h>

#define BB 64
#define RR 32
#define NN 16384
#define DD 64
#define OO 8
#define CHUNKS 16
#define CHUNK (NN / CHUNKS)   // 1024

// Scratch (allocation-free rule: __device__ globals)
__device__ float g_s[BB * DD];   // sum of fmask * normalized context rows
__device__ int   g_cnt[BB];      // nvalid per batch
__device__ int   g_is_u8;        // 1 if masks are byte-packed uint8, 0 if int32

__global__ void zero_kernel() {
    int t = threadIdx.x;
    for (int j = t; j < BB * DD; j += blockDim.x) g_s[j] = 0.0f;
    if (t < BB) g_cnt[t] = 0;
    if (t == 0) g_is_u8 = 0;
}

// Detect mask dtype: scan first B*N/4 words (valid for either dtype).
// uint8-packed bools almost surely produce a word value > 1.
__global__ void detect_kernel(const unsigned int* __restrict__ adj_words) {
    const int nwords = BB * NN / 4;  // 262144
    int found = 0;
    for (int i = blockIdx.x * blockDim.x + threadIdx.x; i < nwords;
         i += gridDim.x * blockDim.x)
        found |= (adj_words[i] > 1u);
    if (__syncthreads_or(found) && threadIdx.x == 0) atomicOr(&g_is_u8, 1);
}

// One block per (batch, N-chunk). Scan masks, compact valid indices,
// gather+normalize only valid rows, reduce into g_s / g_cnt.
__global__ __launch_bounds__(256) void reduce_kernel(
    const float* __restrict__ h_context,      // [B,N,D]
    const int* __restrict__ center_o,         // [B]
    const int* __restrict__ o_types,          // [B,N]
    const void* __restrict__ adj_raw,         // [B,N] bool (u8 or i32)
    const void* __restrict__ two_raw)         // [B,N] bool (u8 or i32)
{
    const int b = blockIdx.x / CHUNKS;
    const int c = blockIdx.x % CHUNKS;
    const int n0 = c * CHUNK;

    __shared__ int   s_idx[CHUNK];
    __shared__ int   s_cnt;
    __shared__ float s_acc[DD];

    const int tid = threadIdx.x;
    if (tid == 0) s_cnt = 0;
    if (tid < DD) s_acc[tid] = 0.0f;
    __syncthreads();

    const int is_u8 = g_is_u8;
    const int co = center_o[b];
    const size_t base = (size_t)b * NN;

    const unsigned char* adj8 = (const unsigned char*)adj_raw;
    const unsigned char* two8 = (const unsigned char*)two_raw;
    const int* adj32 = (const int*)adj_raw;
    const int* two32 = (const int*)two_raw;

    // Phase A: mask scan + compaction (coalesced strided reads)
    for (int n = n0 + tid; n < n0 + CHUNK; n += blockDim.x) {
        const size_t i = base + n;
        bool hop = is_u8 ? ((adj8[i] | two8[i]) != 0)
                         : ((adj32[i] | two32[i]) != 0);
        if (hop && (o_types[i] == co)) {
            int p = atomicAdd(&s_cnt, 1);
            s_idx[p] = n;
        }
    }
    __syncthreads();

    const int cnt = s_cnt;
    const int warp = tid >> 5;
    const int lane = tid & 31;
    const int nwarps = blockDim.x >> 5;

    // Phase B: one warp per valid row. Each lane holds 2 of the 64 dims.
    float a0 = 0.0f, a1 = 0.0f;
    for (int k = warp; k < cnt; k += nwarps) {
        const int n = s_idx[k];
        const float2 v =
            reinterpret_cast<const float2*>(h_context + (base + n) * DD)[lane];
        float sq = v.x * v.x + v.y * v.y;
        #pragma unroll
        for (int o = 16; o; o >>= 1) sq += __shfl_xor_sync(0xffffffffu, sq, o);
        const float sc = rsqrtf(fmaxf(sq, 1e-12f));
        a0 += sc * v.x;
        a1 += sc * v.y;
    }
    // cross-warp reduce into shared
    if (cnt > 0) {
        atomicAdd(&s_acc[2 * lane + 0], a0);
        atomicAdd(&s_acc[2 * lane + 1], a1);
    }
    __syncthreads();

    if (tid < DD && s_acc[tid] != 0.0f) atomicAdd(&g_s[b * DD + tid], s_acc[tid]);
    if (tid == 0 && cnt > 0) atomicAdd(&g_cnt[b], cnt);
}

// One warp per (b,r): normalize l_local row, dot with g_s[b], final formula.
__global__ __launch_bounds__(256) void final_kernel(
    const float* __restrict__ l_local,    // [B,R,D]
    const float* __restrict__ lambda_so,  // [R,O]
    const int* __restrict__ center_o,     // [B]
    float* __restrict__ out)              // [B,R]
{
    const int gw = (blockIdx.x * blockDim.x + threadIdx.x) >> 5;
    const int lane = threadIdx.x & 31;
    if (gw >= BB * RR) return;
    const int b = gw / RR;
    const int r = gw % RR;

    const float2 v =
        reinterpret_cast<const float2*>(l_local + ((size_t)b * RR + r) * DD)[lane];
    const float2 s = reinterpret_cast<const float2*>(g_s + b * DD)[lane];

    float sq = v.x * v.x + v.y * v.y;
    float dp = v.x * s.x + v.y * s.y;
    #pragma unroll
    for (int o = 16; o; o >>= 1) {
        sq += __shfl_xor_sync(0xffffffffu, sq, o);
        dp += __shfl_xor_sync(0xffffffffu, dp, o);
    }

    if (lane == 0) {
        const float inv = rsqrtf(fmaxf(sq, 1e-12f));
        const float nv = (float)g_cnt[b];
        const float avg = dp * inv / fmaxf(nv, 1e-9f);
        const float lv = lambda_so[r * OO + center_o[b]];
        out[gw] = fmaxf(lv / fmaxf(nv, 1.0f), 0.0f) * (1.0f - avg);
    }
}

extern "C" void kernel_launch(void* const* d_in, const int* in_sizes, int n_in,
                              void* d_out, int out_size) {
    const float* l_local   = (const float*)d_in[0];   // [B,R,D]
    const float* h_context = (const float*)d_in[1];   // [B,N,D]
    const float* lambda_so = (const float*)d_in[2];   // [R,O]
    const int*   center_o  = (const int*)d_in[3];     // [B]
    const int*   o_types   = (const int*)d_in[4];     // [B,N]
    const void*  adj_mask  = d_in[5];                 // [B,N] bool (dtype detected)
    const void*  two_hop   = d_in[6];                 // [B,N] bool (dtype detected)
    float* out = (float*)d_out;

    zero_kernel<<<1, 256>>>();
    detect_kernel<<<128, 256>>>((const unsigned int*)adj_mask);
    reduce_kernel<<<BB * CHUNKS, 256>>>(h_context, center_o, o_types, adj_mask, two_hop);
    final_kernel<<<(BB * RR * 32 + 255) / 256, 256>>>(l_local, lambda_so, center_o, out);
}

// round 4
// speedup vs baseline: 1.3488x; 1.3488x over previous
#include <cuda_runtime.h>
#include <cuda_bf16.h>
#include <stdint.h>

#define BB 64
#define RR 32
#define NN 16384
#define DD 64
#define OO 8
#define CHUNKS 16
#define CHUNK (NN / CHUNKS)   // 1024
#define THREADS 256

// Scratch (__device__ globals: allocation-free rule). Zero-initialized at load;
// the last block per batch restores zeros after use, so every graph replay
// starts from the same state.
__device__ float g_s[BB * DD];
__device__ int   g_cnt[BB];
__device__ int   g_arrive[BB];

__global__ __launch_bounds__(THREADS) void fused_kernel(
    const float* __restrict__ h_context,   // [B,N,D]
    const float* __restrict__ l_local,     // [B,R,D]
    const float* __restrict__ lambda_so,   // [R,O]
    const int*   __restrict__ center_o,    // [B]
    const int*   __restrict__ o_types,     // [B,N]
    const int*   __restrict__ adj,         // [B,N] bool as int32
    const int*   __restrict__ two,         // [B,N] bool as int32
    float*       __restrict__ out)         // [B,R]
{
    const int b = blockIdx.x >> 4;         // / CHUNKS
    const int c = blockIdx.x & (CHUNKS - 1);

    __shared__ int   s_idx[CHUNK];
    __shared__ float s_acc[DD];
    __shared__ float s_vec[DD];
    __shared__ int   s_cnt;
    __shared__ int   s_last;
    __shared__ int   s_nv;

    const int tid = threadIdx.x;
    if (tid == 0) s_cnt = 0;
    if (tid < DD) s_acc[tid] = 0.0f;
    __syncthreads();

    const int co = __ldg(&center_o[b]);
    const int base = b * NN + c * CHUNK;

    // ---- Phase A: vectorized mask scan + compaction (int4: 4 elems/thread) ----
    {
        const int4 t4 = *reinterpret_cast<const int4*>(o_types + base + tid * 4);
        const int4 a4 = *reinterpret_cast<const int4*>(adj     + base + tid * 4);
        const int4 w4 = *reinterpret_cast<const int4*>(two     + base + tid * 4);
        const int n0 = c * CHUNK + tid * 4;
        if ((a4.x | w4.x) && t4.x == co) s_idx[atomicAdd(&s_cnt, 1)] = n0 + 0;
        if ((a4.y | w4.y) && t4.y == co) s_idx[atomicAdd(&s_cnt, 1)] = n0 + 1;
        if ((a4.z | w4.z) && t4.z == co) s_idx[atomicAdd(&s_cnt, 1)] = n0 + 2;
        if ((a4.w | w4.w) && t4.w == co) s_idx[atomicAdd(&s_cnt, 1)] = n0 + 3;
    }
    __syncthreads();

    const int cnt  = s_cnt;
    const int warp = tid >> 5;
    const int lane = tid & 31;

    // ---- Phase B: one warp per valid row; lane holds 2 of 64 dims ----
    float a0 = 0.0f, a1 = 0.0f;
    for (int k = warp; k < cnt; k += 8) {
        const int n = s_idx[k];
        const float2 v =
            reinterpret_cast<const float2*>(h_context + ((size_t)b * NN + n) * DD)[lane];
        float sq = v.x * v.x + v.y * v.y;
        #pragma unroll
        for (int o = 16; o; o >>= 1) sq += __shfl_xor_sync(0xffffffffu, sq, o);
        const float sc = rsqrtf(fmaxf(sq, 1e-12f));
        a0 += sc * v.x;
        a1 += sc * v.y;
    }
    if (cnt > 0) {
        atomicAdd(&s_acc[2 * lane + 0], a0);
        atomicAdd(&s_acc[2 * lane + 1], a1);
    }
    __syncthreads();

    // ---- Global accumulation ----
    if (tid < DD && s_acc[tid] != 0.0f) atomicAdd(&g_s[b * DD + tid], s_acc[tid]);
    if (tid == 0 && cnt > 0) atomicAdd(&g_cnt[b], cnt);
    __threadfence();
    __syncthreads();

    if (tid == 0)
        s_last = (atomicAdd(&g_arrive[b], 1) == CHUNKS - 1);
    __syncthreads();
    if (!s_last) return;

    // ---- Last block for batch b: epilogue ----
    if (tid < DD) s_vec[tid] = __ldcg(&g_s[b * DD + tid]);
    if (tid == 0) s_nv = __ldcg(&g_cnt[b]);
    __syncthreads();

    // Reset scratch for the next graph replay (stream-ordered visibility).
    if (tid < DD) g_s[b * DD + tid] = 0.0f;
    if (tid == 0) { g_cnt[b] = 0; g_arrive[b] = 0; }

    const float nv = (float)s_nv;
    const float inv_nv_avg = 1.0f / fmaxf(nv, 1e-9f);
    const float inv_nv_lam = 1.0f / fmaxf(nv, 1.0f);

    // 8 warps x 4 rows each = 32 rows
    for (int r = warp; r < RR; r += 8) {
        const float2 v =
            reinterpret_cast<const float2*>(l_local + ((size_t)b * RR + r) * DD)[lane];
        const float2 s = reinterpret_cast<const float2*>(s_vec)[lane];
        float sq = v.x * v.x + v.y * v.y;
        float dp = v.x * s.x + v.y * s.y;
        #pragma unroll
        for (int o = 16; o; o >>= 1) {
            sq += __shfl_xor_sync(0xffffffffu, sq, o);
            dp += __shfl_xor_sync(0xffffffffu, dp, o);
        }
        if (lane == 0) {
            const float inv = rsqrtf(fmaxf(sq, 1e-12f));
            const float avg = dp * inv * inv_nv_avg;
            const float lv  = lambda_so[r * OO + co];
            out[b * RR + r] = fmaxf(lv * inv_nv_lam, 0.0f) * (1.0f - avg);
        }
    }
}

extern "C" void kernel_launch(void* const* d_in, const int* in_sizes, int n_in,
                              void* d_out, int out_size) {
    const float* l_local   = (const float*)d_in[0];
    const float* h_context = (const float*)d_in[1];
    const float* lambda_so = (const float*)d_in[2];
    const int*   center_o  = (const int*)d_in[3];
    const int*   o_types   = (const int*)d_in[4];
    const int*   adj_mask  = (const int*)d_in[5];   // bool widened to int32 (R1/R2 differential)
    const int*   two_hop   = (const int*)d_in[6];
    float* out = (float*)d_out;

    fused_kernel<<<BB * CHUNKS, THREADS>>>(h_context, l_local, lambda_so,
                                           center_o, o_types, adj_mask, two_hop, out);
}

// round 6
// speedup vs baseline: 1.6571x; 1.2286x over previous
#include <cuda_runtime.h>
#include <cuda_bf16.h>
#include <stdint.h>

#define BB 64
#define RR 32
#define NN 16384
#define DD 64
#define OO 8
#define THREADS 1024
#define NW (THREADS / 32)   // 32 warps
#define CAP 2048

__global__ __launch_bounds__(THREADS) void fused_kernel(
    const float* __restrict__ h_context,   // [B,N,D]
    const float* __restrict__ l_local,     // [B,R,D]
    const float* __restrict__ lambda_so,   // [R,O]
    const int*   __restrict__ center_o,    // [B]
    const int*   __restrict__ o_types,     // [B,N]
    const int*   __restrict__ adj,         // [B,N] bool as int32
    const int*   __restrict__ two,         // [B,N] bool as int32
    float*       __restrict__ out)         // [B,R]
{
    const int b    = blockIdx.x;
    const int tid  = threadIdx.x;
    const int wid  = tid >> 5;
    const int lane = tid & 31;

    __shared__ int   s_idx[CAP];
    __shared__ float s_part[NW * DD];
    __shared__ float s_vec[DD];
    __shared__ int   s_cnt;

    // Early independent load: this warp's l_local row (r = wid). Latency hides
    // behind the entire scan phase.
    const float2 lv2 =
        reinterpret_cast<const float2*>(l_local + ((size_t)b * RR + wid) * DD)[lane];
    const int co = __ldg(&center_o[b]);

    if (tid == 0) s_cnt = 0;
    __syncthreads();

    // ---- Phase A: mask scan, MLP=12 (4 x int4 per array per thread) ----
    const int4* ot4 = reinterpret_cast<const int4*>(o_types + b * NN);
    const int4* ad4 = reinterpret_cast<const int4*>(adj     + b * NN);
    const int4* tw4 = reinterpret_cast<const int4*>(two     + b * NN);

    int4 tt[4], aa[4], ww[4];
    #pragma unroll
    for (int j = 0; j < 4; j++) {
        tt[j] = ot4[tid + j * 1024];
        aa[j] = ad4[tid + j * 1024];
        ww[j] = tw4[tid + j * 1024];
    }
    #pragma unroll
    for (int j = 0; j < 4; j++) {
        const int n0 = (j * 1024 + tid) * 4;
        if ((aa[j].x | ww[j].x) && tt[j].x == co) { int p = atomicAdd(&s_cnt, 1); if (p < CAP) s_idx[p] = n0 + 0; }
        if ((aa[j].y | ww[j].y) && tt[j].y == co) { int p = atomicAdd(&s_cnt, 1); if (p < CAP) s_idx[p] = n0 + 1; }
        if ((aa[j].z | ww[j].z) && tt[j].z == co) { int p = atomicAdd(&s_cnt, 1); if (p < CAP) s_idx[p] = n0 + 2; }
        if ((aa[j].w | ww[j].w) && tt[j].w == co) { int p = atomicAdd(&s_cnt, 1); if (p < CAP) s_idx[p] = n0 + 3; }
    }
    __syncthreads();
    int cnt = s_cnt;
    if (cnt > CAP) cnt = CAP;

    // ---- Phase B: gather + normalize. Half-warp per row (16 lanes x float4),
    //      2 rows per warp-iteration -> 2 iterations for cnt ~ 122.
    const int half = lane >> 4;
    const int l16  = lane & 15;
    float a0 = 0.0f, a1 = 0.0f, a2 = 0.0f, a3 = 0.0f;

    for (int k0 = wid * 2; k0 < cnt; k0 += NW * 2) {
        const int k = k0 + half;
        float4 v = make_float4(0.0f, 0.0f, 0.0f, 0.0f);
        if (k < cnt) {
            const int n = s_idx[k];
            v = reinterpret_cast<const float4*>(
                    h_context + ((size_t)b * NN + n) * DD)[l16];
        }
        float sq = v.x * v.x + v.y * v.y + v.z * v.z + v.w * v.w;
        sq += __shfl_xor_sync(0xffffffffu, sq, 8);
        sq += __shfl_xor_sync(0xffffffffu, sq, 4);
        sq += __shfl_xor_sync(0xffffffffu, sq, 2);
        sq += __shfl_xor_sync(0xffffffffu, sq, 1);
        const float sc = rsqrtf(fmaxf(sq, 1e-12f));
        a0 += sc * v.x; a1 += sc * v.y; a2 += sc * v.z; a3 += sc * v.w;
    }
    // combine the two half-warps (same dims), lanes 0-15 hold full-warp sums
    a0 += __shfl_xor_sync(0xffffffffu, a0, 16);
    a1 += __shfl_xor_sync(0xffffffffu, a1, 16);
    a2 += __shfl_xor_sync(0xffffffffu, a2, 16);
    a3 += __shfl_xor_sync(0xffffffffu, a3, 16);
    if (lane < 16)
        reinterpret_cast<float4*>(s_part + wid * DD)[l16] =
            make_float4(a0, a1, a2, a3);
    __syncthreads();

    // ---- Cross-warp tree sum (no atomics) ----
    if (tid < DD) {
        float s = 0.0f;
        #pragma unroll
        for (int w2 = 0; w2 < NW; w2++) s += s_part[w2 * DD + tid];
        s_vec[tid] = s;
    }
    __syncthreads();

    // ---- Epilogue: warp w computes output row r = w ----
    const float2 sv = reinterpret_cast<const float2*>(s_vec)[lane];
    float sq = lv2.x * lv2.x + lv2.y * lv2.y;
    float dp = lv2.x * sv.x + lv2.y * sv.y;
    #pragma unroll
    for (int o = 16; o; o >>= 1) {
        sq += __shfl_xor_sync(0xffffffffu, sq, o);
        dp += __shfl_xor_sync(0xffffffffu, dp, o);
    }
    if (lane == 0) {
        const float nv  = (float)cnt;
        const float inv = rsqrtf(fmaxf(sq, 1e-12f));
        const float avg = dp * inv / fmaxf(nv, 1e-9f);
        const float lv  = lambda_so[wid * OO + co];
        out[b * RR + wid] = fmaxf(lv / fmaxf(nv, 1.0f), 0.0f) * (1.0f - avg);
    }
}

extern "C" void kernel_launch(void* const* d_in, const int* in_sizes, int n_in,
                              void* d_out, int out_size) {
    const float* l_local   = (const float*)d_in[0];
    const float* h_context = (const float*)d_in[1];
    const float* lambda_so = (const float*)d_in[2];
    const int*   center_o  = (const int*)d_in[3];
    const int*   o_types   = (const int*)d_in[4];
    const int*   adj_mask  = (const int*)d_in[5];
    const int*   two_hop   = (const int*)d_in[6];
    float* out = (float*)d_out;

    fused_kernel<<<BB, THREADS>>>(h_context, l_local, lambda_so,
                                  center_o, o_types, adj_mask, two_hop, out);
}